// round 15
// baseline (speedup 1.0000x reference)
#include <cuda_runtime.h>
#include <cuda_fp16.h>
#include <cstdint>
#include <cstddef>

// Problem constants: T=4096, H=I=2048, E=8, top-2
#define TTOK 4096
#define HD   2048
#define NE   8
#define NSLOT (2*TTOK)
#define NSLOTP 9216
#define MTMAX (NSLOTP/128)     // 72

#define BM 128
#define BKC 64
#define NCHUNK (HD/BKC)        // 32
#define NSTG 3
#define NTHR 256

// gate+up: 128M x 128N dual-B
#define GU_ABLK 18432          // 128 rows x 144B
#define GU_BBLK 17408          // 64 rows x 272B
#define GU_STG  (GU_ABLK + 2*GU_BBLK)   // 53248
// down: 128M x 256N
#define DN_ABLK 18432
#define DN_BBLK 33792          // 64 rows x 528B
#define DN_STG  (DN_ABLK + DN_BBLK)     // 52224
#define RING_SMEM (NSTG*GU_STG)         // 159744

#define NPERS 148
#define IT_TOT 2169

// item types
#define TY_XC  0
#define TY_RT  1
#define TY_SC  2
#define TY_W1  3
#define TY_W3  4
#define TY_XG  5
#define TY_GU  6
#define TY_W2  7
#define TY_DN  8

// ---------------- device scratch ----------------
__device__ int   g_counts[NE];
__device__ int   g_offs[NE];
__device__ int   g_ends[NE];
__device__ int   g_cursor[NE];
__device__ int   g_top_idx[NSLOT];
__device__ float g_top_scale[NSLOT];
__device__ int   g_slot_tok[NSLOTP];
__device__ int   g_tok_pos[NSLOT];

// queue + dependency state
__device__ int   g_items[IT_TOT];
__device__ int   g_work;
__device__ int   g_nmt;
__device__ int   g_mt_e[MTMAX];
__device__ int   g_rt_done, g_xc_done, g_scan_done, g_dn_done;
__device__ int   g_xg_done[MTMAX];
__device__ int   g_gu_done[MTMAX];
__device__ int   g_w1c[NE*16];
__device__ int   g_w3c[NE*16];
__device__ int   g_w2c[NE*8];

__device__ __align__(16) __half g_x16[(size_t)TTOK*HD];
__device__ __align__(16) __half g_w1t[(size_t)NE*16*32*(GU_BBLK/2)];
__device__ __align__(16) __half g_w3t[(size_t)NE*16*32*(GU_BBLK/2)];
__device__ __align__(16) __half g_w2t[(size_t)NE*8*32*(DN_BBLK/2)];
__device__ __align__(16) __half g_xg[(size_t)MTMAX*32*(GU_ABLK/2)];
__device__ __align__(16) __half g_actt[(size_t)MTMAX*32*(DN_ABLK/2)];
__device__ __align__(16) float  g_gbuf[(size_t)NSLOTP*HD];

// ---------------- helpers ----------------
__device__ __forceinline__ uint32_t smem_u32(const void* p) {
    return (uint32_t)__cvta_generic_to_shared(p);
}
__device__ __forceinline__ void mbar_init(uint32_t a, uint32_t cnt) {
    asm volatile("mbarrier.init.shared.b64 [%0], %1;" :: "r"(a), "r"(cnt) : "memory");
}
__device__ __forceinline__ void mbar_expect(uint32_t a, uint32_t bytes) {
    asm volatile("mbarrier.arrive.expect_tx.shared.b64 _, [%0], %1;"
                 :: "r"(a), "r"(bytes) : "memory");
}
__device__ __forceinline__ void mbar_wait(uint32_t a, uint32_t parity) {
    asm volatile(
        "{\n\t.reg .pred P;\n\t"
        "WL_%=:\n\t"
        "mbarrier.try_wait.parity.shared::cta.b64 P, [%0], %1;\n\t"
        "@P bra WD_%=;\n\t"
        "bra WL_%=;\n\t"
        "WD_%=:\n\t}"
        :: "r"(a), "r"(parity) : "memory");
}
__device__ __forceinline__ void bulk_g2s(uint32_t dst, const void* src,
                                         uint32_t bytes, uint32_t mbar) {
    asm volatile(
        "cp.async.bulk.shared::cta.global.mbarrier::complete_tx::bytes [%0], [%1], %2, [%3];"
        :: "r"(dst), "l"(src), "r"(bytes), "r"(mbar) : "memory");
}
__device__ __forceinline__ void ldsm_x4(uint32_t (&r)[4], uint32_t addr) {
    asm volatile("ldmatrix.sync.aligned.m8n8.x4.shared.b16 {%0,%1,%2,%3}, [%4];\n"
                 : "=r"(r[0]), "=r"(r[1]), "=r"(r[2]), "=r"(r[3]) : "r"(addr));
}
__device__ __forceinline__ void ldsm_x4_t(uint32_t (&r)[4], uint32_t addr) {
    asm volatile("ldmatrix.sync.aligned.m8n8.x4.trans.shared.b16 {%0,%1,%2,%3}, [%4];\n"
                 : "=r"(r[0]), "=r"(r[1]), "=r"(r[2]), "=r"(r[3]) : "r"(addr));
}
__device__ __forceinline__ void mma16816(float (&c)[4], const uint32_t (&a)[4],
                                         uint32_t b0, uint32_t b1) {
    asm volatile(
        "mma.sync.aligned.m16n8k16.row.col.f32.f16.f16.f32 "
        "{%0,%1,%2,%3}, {%4,%5,%6,%7}, {%8,%9}, {%0,%1,%2,%3};\n"
        : "+f"(c[0]), "+f"(c[1]), "+f"(c[2]), "+f"(c[3])
        : "r"(a[0]), "r"(a[1]), "r"(a[2]), "r"(a[3]), "r"(b0), "r"(b1));
}
__device__ __forceinline__ float silu_mul(float g, float u) {
    return u * (g / (1.f + __expf(-g)));
}
__device__ __forceinline__ uint32_t h2u(__half2 h) { return *(uint32_t*)&h; }
__device__ __forceinline__ int ldvol(const int* p) {
    int v;
    asm volatile("ld.volatile.global.b32 %0, [%1];" : "=r"(v) : "l"(p));
    return v;
}
__device__ __forceinline__ uint4 pack16(float4 v0, float4 v1) {
    uint4 p;
    p.x = h2u(__floats2half2_rn(v0.x, v0.y));
    p.y = h2u(__floats2half2_rn(v0.z, v0.w));
    p.z = h2u(__floats2half2_rn(v1.x, v1.y));
    p.w = h2u(__floats2half2_rn(v1.z, v1.w));
    return p;
}

// ---------------- init: flags + software-pipelined work table ----------------
__global__ void init_small_kernel() {
    int i = threadIdx.x;
    if (i < NE) { g_counts[i] = 0; g_cursor[i] = 0; }
    if (i == 0) { g_work = 0; g_rt_done = 0; g_xc_done = 0; g_scan_done = 0; g_dn_done = 0; }
    if (i < MTMAX) { g_xg_done[i] = 0; g_gu_done[i] = 0; }
    if (i < NE*16) { g_w1c[i] = 0; g_w3c[i] = 0; }
    if (i < NE*8) g_w2c[i] = 0;
    if (i == 0) {
        int n = 0;
#define ADDIT(t, a, b) g_items[n++] = ((t) << 16) | ((a) << 8) | (b)
        for (int j = 0; j < 16; j++) ADDIT(TY_XC, j, 0);
        for (int j = 0; j < 32; j++) ADDIT(TY_RT, j, 0);
        for (int e = 0; e < NE; e++) ADDIT(TY_W1, e, 0);
        for (int e = 0; e < NE; e++) ADDIT(TY_W3, e, 0);
        ADDIT(TY_SC, 0, 0);
        for (int e = 0; e < NE; e++) ADDIT(TY_W1, e, 1);
        for (int e = 0; e < NE; e++) ADDIT(TY_W3, e, 1);
        for (int m = 0; m < MTMAX; m++) ADDIT(TY_XG, m, 0);
        for (int nt = 0; nt < 16; nt++) {
            for (int m = 0; m < MTMAX; m++) ADDIT(TY_GU, m, nt);
            if (nt + 2 < 16) {
                for (int e = 0; e < NE; e++) ADDIT(TY_W1, e, nt + 2);
                for (int e = 0; e < NE; e++) ADDIT(TY_W3, e, nt + 2);
            }
            if (nt >= 8) {
                for (int e = 0; e < NE; e++) ADDIT(TY_W2, e, nt - 8);
            }
        }
        for (int nt2 = 0; nt2 < 8; nt2++)
            for (int m = 0; m < MTMAX; m++) ADDIT(TY_DN, m, nt2);
    }
}

// ---------------- item bodies (256 threads) ----------------
// router item: 128 tokens = 8 warps x 4 tokens x 4 passes
__device__ void rt_item(const float* __restrict__ x, const float* __restrict__ rw,
                        int it, int tid) {
    const int warp = tid >> 5, lane = tid & 31;
#pragma unroll
    for (int pass = 0; pass < 4; pass++) {
        const int t0 = it * 128 + pass * 32 + warp * 4;
        float acc[4][NE];
#pragma unroll
        for (int j = 0; j < 4; j++)
#pragma unroll
            for (int e = 0; e < NE; e++) acc[j][e] = 0.f;
        const float* xr = x + (size_t)t0 * HD;
        for (int h = lane; h < HD; h += 32) {
            float4 r0 = *(const float4*)(rw + (size_t)h * NE);
            float4 r1 = *(const float4*)(rw + (size_t)h * NE + 4);
            float rv[NE] = {r0.x, r0.y, r0.z, r0.w, r1.x, r1.y, r1.z, r1.w};
#pragma unroll
            for (int j = 0; j < 4; j++) {
                float xv = xr[(size_t)j * HD + h];
#pragma unroll
                for (int e = 0; e < NE; e++) acc[j][e] = fmaf(xv, rv[e], acc[j][e]);
            }
        }
#pragma unroll
        for (int j = 0; j < 4; j++)
#pragma unroll
            for (int e = 0; e < NE; e++) {
#pragma unroll
                for (int o = 16; o; o >>= 1)
                    acc[j][e] += __shfl_xor_sync(0xffffffffu, acc[j][e], o);
            }
        if (lane == 0) {
#pragma unroll
            for (int j = 0; j < 4; j++) {
                int t = t0 + j;
                int i0 = 0; float v0 = acc[j][0];
#pragma unroll
                for (int e = 1; e < NE; e++) if (acc[j][e] > v0) { v0 = acc[j][e]; i0 = e; }
                int i1 = -1; float v1 = -3.4e38f;
#pragma unroll
                for (int e = 0; e < NE; e++)
                    if (e != i0 && acc[j][e] > v1) { v1 = acc[j][e]; i1 = e; }
                float ex = expf(v1 - v0);
                float inv = 1.f / (1.f + ex);
                g_top_idx[2*t]   = i0; g_top_scale[2*t]   = inv;
                g_top_idx[2*t+1] = i1; g_top_scale[2*t+1] = ex * inv;
                atomicAdd(&g_counts[i0], 1);
                atomicAdd(&g_counts[i1], 1);
            }
        }
    }
}

__device__ void xc_item(const float* __restrict__ x, int i, int tid) {
    const float4* s4 = (const float4*)x;
    __half2* d2 = (__half2*)g_x16;
#pragma unroll 4
    for (int j = 0; j < 512; j++) {
        size_t idx = (size_t)i * 131072 + (size_t)j * NTHR + tid;
        float4 v = s4[idx];
        d2[2*idx]   = __floats2half2_rn(v.x, v.y);
        d2[2*idx+1] = __floats2half2_rn(v.z, v.w);
    }
}

__device__ void scan_item(int tid) {
    if (tid == 0) {
        int o = 0;
        for (int e = 0; e < NE; e++) {
            g_offs[e] = o; g_cursor[e] = o; g_ends[e] = o + g_counts[e];
            int padded = (g_counts[e] + 127) & ~127;
            for (int m = o >> 7; m < (o + padded) >> 7; m++) g_mt_e[m] = e;
            o += padded;
        }
        g_nmt = o >> 7;
        for (int m = o >> 7; m < MTMAX; m++) g_mt_e[m] = 0;
    }
    __syncthreads();
    for (int i = tid; i < NSLOTP; i += NTHR) g_slot_tok[i] = -1;
    __syncthreads();
    for (int i = tid; i < NSLOT; i += NTHR) {
        int e = g_top_idx[i];
        int pos = atomicAdd(&g_cursor[e], 1);
        g_slot_tok[pos] = i >> 1;
        g_tok_pos[i] = pos;
    }
}

__device__ void wcvt_gu(const float* __restrict__ src, char* base, int e, int nt, int tid) {
    const float4* s4 = (const float4*)(src + (size_t)e * HD * HD);
#pragma unroll 4
    for (int i = 0; i < 128; i++) {
        int u = i * NTHR + tid;
        int k = u >> 4, nl = u & 15;
        const float4* s = s4 + (size_t)k * 512 + (nt * 16 + nl) * 2;
        uint4 pkt = pack16(s[0], s[1]);
        char* dst = base + ((size_t)((e*16 + nt)*32 + (k >> 6)))*GU_BBLK
                  + (size_t)(k & 63)*272 + (size_t)nl*16;
        *(uint4*)dst = pkt;
    }
}

__device__ void wcvt_dn(const float* __restrict__ w2, int e, int nt2, int tid) {
    const float4* s4 = (const float4*)(w2 + (size_t)e * HD * HD);
#pragma unroll 4
    for (int i = 0; i < 256; i++) {
        int u = i * NTHR + tid;
        int k = u >> 5, nl = u & 31;
        const float4* s = s4 + (size_t)k * 512 + (nt2 * 32 + nl) * 2;
        uint4 pkt = pack16(s[0], s[1]);
        char* dst = (char*)g_w2t + ((size_t)((e*8 + nt2)*32 + (k >> 6)))*DN_BBLK
                  + (size_t)(k & 63)*528 + (size_t)nl*16;
        *(uint4*)dst = pkt;
    }
}

__device__ void xg_tile(int m, int tid) {
#pragma unroll 4
    for (int i = 0; i < 128; i++) {
        int u = i * NTHR + tid;
        int seg = u & 7, c = (u >> 3) & 31, row = u >> 8;
        int tok = g_slot_tok[m * 128 + row];
        uint4 v = make_uint4(0, 0, 0, 0);
        if (tok >= 0) v = *(const uint4*)(g_x16 + (size_t)tok * HD + c * 64 + seg * 8);
        char* dst = (char*)g_xg + ((size_t)m * 32 + c) * GU_ABLK
                  + (size_t)row * 144 + (size_t)seg * 16;
        *(uint4*)dst = v;
    }
}

// ---- GU tile: 8 warps, warp tile 64M x 32N x 2 mats ----
__device__ void gu_tile(char* sm, uint64_t* bars, int m, int nt, int tid) {
    const int e = g_mt_e[m];
    const int row0 = m * 128;
    const int rowEnd = g_ends[e];
    const int n0 = nt * 128;

    const char* aBase  = (const char*)g_xg  + (size_t)m * 32 * GU_ABLK;
    const char* b1Base = (const char*)g_w1t + (size_t)(e*16 + nt) * 32 * GU_BBLK;
    const char* b3Base = (const char*)g_w3t + (size_t)(e*16 + nt) * 32 * GU_BBLK;

    const uint32_t sb = smem_u32(sm);
    const uint32_t bb = smem_u32(bars);

    if (tid == 0) {
#pragma unroll
        for (int s = 0; s < NSTG; s++) mbar_init(bb + 8*s, 1);
    }
    __syncthreads();
    if (tid == 0) {
#pragma unroll
        for (int p = 0; p < 2; p++) {
            uint32_t st = sb + p * GU_STG, mb = bb + 8*p;
            mbar_expect(mb, GU_STG);
            bulk_g2s(st,                     aBase  + (size_t)p * GU_ABLK, GU_ABLK, mb);
            bulk_g2s(st + GU_ABLK,           b1Base + (size_t)p * GU_BBLK, GU_BBLK, mb);
            bulk_g2s(st + GU_ABLK + GU_BBLK, b3Base + (size_t)p * GU_BBLK, GU_BBLK, mb);
        }
    }

    const int wid = tid >> 5, lane = tid & 31;
    const int wm = wid & 1, wn = wid >> 1;          // 2 M-groups x 4 N-groups
    const int ar = lane & 15, ac = (lane >> 4) * 8;
    const int br = lane & 15, bc = (lane >> 4) * 8;

    float accG[4][4][4], accU[4][4][4];
#pragma unroll
    for (int mt = 0; mt < 4; mt++)
#pragma unroll
        for (int q4 = 0; q4 < 4; q4++)
#pragma unroll
            for (int q = 0; q < 4; q++) { accG[mt][q4][q] = 0.f; accU[mt][q4][q] = 0.f; }

    for (int c = 0; c < NCHUNK; c++) {
        int s = c % NSTG;
        mbar_wait(bb + 8*s, (c / NSTG) & 1);
        __syncthreads();
        if (tid == 0 && c + 2 < NCHUNK) {
            int s2 = (c + 2) % NSTG;
            uint32_t st = sb + s2 * GU_STG, mb = bb + 8*s2;
            mbar_expect(mb, GU_STG);
            bulk_g2s(st,                     aBase  + (size_t)(c+2) * GU_ABLK, GU_ABLK, mb);
            bulk_g2s(st + GU_ABLK,           b1Base + (size_t)(c+2) * GU_BBLK, GU_BBLK, mb);
            bulk_g2s(st + GU_ABLK + GU_BBLK, b3Base + (size_t)(c+2) * GU_BBLK, GU_BBLK, mb);
        }
        uint32_t stb = sb + (uint32_t)s * GU_STG;

#pragma unroll
        for (int kk = 0; kk < 4; kk++) {
            uint32_t a[4][4];
#pragma unroll
            for (int mt = 0; mt < 4; mt++) {
                uint32_t aaddr = stb
                    + (uint32_t)((wm * 64 + mt * 16 + ar) * 144 + (kk * 16 + ac) * 2);
                ldsm_x4(a[mt], aaddr);
            }
            uint32_t brow = (uint32_t)((kk * 16 + br) * 272);
#pragma unroll
            for (int p = 0; p < 2; p++) {
                uint32_t coff = (uint32_t)((wn * 32 + p * 16 + bc) * 2);
                uint32_t b1[4], b3[4];
                ldsm_x4_t(b1, stb + GU_ABLK + brow + coff);
                ldsm_x4_t(b3, stb + GU_ABLK + GU_BBLK + brow + coff);
#pragma unroll
                for (int mt = 0; mt < 4; mt++) {
                    mma16816(accG[mt][2*p],   a[mt], b1[0], b1[1]);
                    mma16816(accG[mt][2*p+1], a[mt], b1[2], b1[3]);
                    mma16816(accU[mt][2*p],   a[mt], b3[0], b3[1]);
                    mma16816(accU[mt][2*p+1], a[mt], b3[2], b3[3]);
                }
            }
        }
    }

    // epilogue: act = silu(g)*u -> fp16, slot-tiled (DN A) layout
    const int rIn = lane >> 2, cIn = (lane & 3) * 2;
#pragma unroll
    for (int mt = 0; mt < 4; mt++) {
#pragma unroll
        for (int half = 0; half < 2; half++) {
            int slot = row0 + wm * 64 + mt * 16 + rIn + half * 8;
            if (slot < rowEnd) {
                int srow = slot & 127, smt = slot >> 7;
#pragma unroll
                for (int q4 = 0; q4 < 4; q4++) {
                    int col = n0 + wn * 32 + q4 * 8 + cIn;
                    int cch = col >> 6, kl = col & 63;
                    __half* dst = g_actt + ((size_t)smt * 32 + cch) * (DN_ABLK/2)
                                + (size_t)srow * 72 + kl;
                    float a0 = silu_mul(accG[mt][q4][half*2],   accU[mt][q4][half*2]);
                    float a1 = silu_mul(accG[mt][q4][half*2+1], accU[mt][q4][half*2+1]);
                    *(__half2*)dst = __floats2half2_rn(a0, a1);
                }
            }
        }
    }
}

// ---- DN tile: 8 warps, warp tile 64M x 64N ----
__device__ void dn_tile(char* sm, uint64_t* bars, int m, int nt, int tid) {
    const int e = g_mt_e[m];
    const int row0 = m * 128;
    const int rowEnd = g_ends[e];
    const int n0 = nt * 256;

    const char* aBase = (const char*)g_actt + (size_t)m * 32 * DN_ABLK;
    const char* bBase = (const char*)g_w2t + (size_t)(e*8 + nt) * 32 * DN_BBLK;

    const uint32_t sb = smem_u32(sm);
    const uint32_t bb = smem_u32(bars);

    if (tid == 0) {
#pragma unroll
        for (int s = 0; s < NSTG; s++) mbar_init(bb + 8*s, 1);
    }
    __syncthreads();
    if (tid == 0) {
#pragma unroll
        for (int p = 0; p < 2; p++) {
            uint32_t st = sb + p * DN_STG, mb = bb + 8*p;
            mbar_expect(mb, DN_STG);
            bulk_g2s(st,           aBase + (size_t)p * DN_ABLK, DN_ABLK, mb);
            bulk_g2s(st + DN_ABLK, bBase + (size_t)p * DN_BBLK, DN_BBLK, mb);
        }
    }

    const int wid = tid >> 5, lane = tid & 31;
    const int wm = wid & 1, wn = wid >> 1;          // 2 M-groups x 4 N-groups (64 cols)
    const int ar = lane & 15, ac = (lane >> 4) * 8;
    const int br = lane & 15, bc = (lane >> 4) * 8;

    float acc[4][8][4];
#pragma unroll
    for (int mt = 0; mt < 4; mt++)
#pragma unroll
        for (int q8 = 0; q8 < 8; q8++)
#pragma unroll
            for (int q = 0; q < 4; q++) acc[mt][q8][q] = 0.f;

    for (int c = 0; c < NCHUNK; c++) {
        int s = c % NSTG;
        mbar_wait(bb + 8*s, (c / NSTG) & 1);
        __syncthreads();
        if (tid == 0 && c + 2 < NCHUNK) {
            int s2 = (c + 2) % NSTG;
            uint32_t st = sb + s2 * DN_STG, mb = bb + 8*s2;
            mbar_expect(mb, DN_STG);
            bulk_g2s(st,           aBase + (size_t)(c+2) * DN_ABLK, DN_ABLK, mb);
            bulk_g2s(st + DN_ABLK, bBase + (size_t)(c+2) * DN_BBLK, DN_BBLK, mb);
        }
        uint32_t stb = sb + (uint32_t)s * DN_STG;

#pragma unroll
        for (int kk = 0; kk < 4; kk++) {
            uint32_t a[4][4];
#pragma unroll
            for (int mt = 0; mt < 4; mt++) {
                uint32_t aaddr = stb
                    + (uint32_t)((wm * 64 + mt * 16 + ar) * 144 + (kk * 16 + ac) * 2);
                ldsm_x4(a[mt], aaddr);
            }
            uint32_t brow = (uint32_t)((kk * 16 + br) * 528);
#pragma unroll
            for (int p = 0; p < 4; p++) {
                uint32_t b[4];
                ldsm_x4_t(b, stb + DN_ABLK + brow
                             + (uint32_t)((wn * 64 + p * 16 + bc) * 2));
#pragma unroll
                for (int mt = 0; mt < 4; mt++) {
                    mma16816(acc[mt][2*p],   a[mt], b[0], b[1]);
                    mma16816(acc[mt][2*p+1], a[mt], b[2], b[3]);
                }
            }
        }
    }

    const int rIn = lane >> 2, cIn = (lane & 3) * 2;
#pragma unroll
    for (int mt = 0; mt < 4; mt++) {
#pragma unroll
        for (int half = 0; half < 2; half++) {
            int slot = row0 + wm * 64 + mt * 16 + rIn + half * 8;
            if (slot < rowEnd) {
                float* Cp = g_gbuf + (size_t)slot * HD + n0 + wn * 64 + cIn;
#pragma unroll
                for (int q8 = 0; q8 < 8; q8++) {
                    float2 v = make_float2(acc[mt][q8][half*2], acc[mt][q8][half*2+1]);
                    *(float2*)(Cp + q8 * 8) = v;
                }
            }
        }
    }
}

// ---------------- persistent table-driven scheduler (256 threads) ----------------
__global__ void __launch_bounds__(NTHR, 1)
moe_persistent(float* __restrict__ out,
               const float* __restrict__ x,  const float* __restrict__ rw,
               const float* __restrict__ w1, const float* __restrict__ w3,
               const float* __restrict__ w2) {
    extern __shared__ __align__(128) char sm[];
    __shared__ __align__(8) uint64_t bars[NSTG];
    __shared__ int sh_w, sh_flag;
    const int tid = threadIdx.x;

    for (;;) {
        if (tid == 0) sh_w = atomicAdd(&g_work, 1);
        __syncthreads();
        int w = sh_w;
        if (w >= IT_TOT) break;
        int item = g_items[w];
        int ty = item >> 16, a = (item >> 8) & 255, b = item & 255;

        switch (ty) {
        case TY_XC:
            xc_item(x, a, tid);
            __threadfence(); __syncthreads();
            if (tid == 0) atomicAdd(&g_xc_done, 1);
            break;
        case TY_RT:
            rt_item(x, rw, a, tid);
            __threadfence(); __syncthreads();
            if (tid == 0) atomicAdd(&g_rt_done, 1);
            break;
        case TY_SC:
            if (tid == 0) { while (ldvol(&g_rt_done) < 32) {} }
            __syncthreads(); __threadfence();
            scan_item(tid);
            __threadfence(); __syncthreads();
            if (tid == 0) atomicExch(&g_scan_done, 1);
            break;
        case TY_W1:
            wcvt_gu(w1, (char*)g_w1t, a, b, tid);
            __threadfence(); __syncthreads();
            if (tid == 0) atomicExch(&g_w1c[a*16 + b], 1);
            break;
        case TY_W3:
            wcvt_gu(w3, (char*)g_w3t, a, b, tid);
            __threadfence(); __syncthreads();
            if (tid == 0) atomicExch(&g_w3c[a*16 + b], 1);
            break;
        case TY_XG:
            if (tid == 0) {
                while (ldvol(&g_scan_done) == 0) {}
                while (ldvol(&g_xc_done) < 16) {}
                sh_flag = (a < g_nmt);
            }
            __syncthreads(); __threadfence();
            if (sh_flag) xg_tile(a, tid);
            __threadfence(); __syncthreads();
            if (tid == 0) atomicExch(&g_xg_done[a], 1);
            break;
        case TY_GU:
            if (tid == 0) {
                while (ldvol(&g_xg_done[a]) == 0) {}
                int e = g_mt_e[a];
                while (ldvol(&g_w1c[e*16 + b]) == 0) {}
                while (ldvol(&g_w3c[e*16 + b]) == 0) {}
                sh_flag = (a < g_nmt);
            }
            __syncthreads(); __threadfence();
            if (sh_flag) gu_tile(sm, bars, a, b, tid);
            __threadfence(); __syncthreads();
            if (tid == 0) atomicAdd(&g_gu_done[a], 1);
            break;
        case TY_W2:
            wcvt_dn(w2, a, b, tid);
            __threadfence(); __syncthreads();
            if (tid == 0) atomicExch(&g_w2c[a*8 + b], 1);
            break;
        default: // TY_DN
            if (tid == 0) {
                while (ldvol(&g_gu_done[a]) < 16) {}
                int e = g_mt_e[a];
                while (ldvol(&g_w2c[e*8 + b]) == 0) {}
                sh_flag = (a < g_nmt);
            }
            __syncthreads(); __threadfence();
            if (sh_flag) dn_tile(sm, bars, a, b, tid);
            __threadfence(); __syncthreads();
            if (tid == 0) atomicAdd(&g_dn_done, 1);
            break;
        }
        __syncthreads();
    }

    // combine: out[t] = s0*y[p0] + s1*y[p1]
    if (tid == 0) { while (ldvol(&g_dn_done) < MTMAX * 8) {} }
    __syncthreads(); __threadfence();
    const int N4 = TTOK * HD / 4;
    for (int i = blockIdx.x * NTHR + tid; i < N4; i += NPERS * NTHR) {
        int t  = i >> 9;
        int h4 = i & 511;
        float s0 = g_top_scale[2*t], s1 = g_top_scale[2*t+1];
        int p0 = g_tok_pos[2*t], p1 = g_tok_pos[2*t+1];
        float4 va = __ldcg((const float4*)(g_gbuf + (size_t)p0 * HD) + h4);
        float4 vb = __ldcg((const float4*)(g_gbuf + (size_t)p1 * HD) + h4);
        float4 o;
        o.x = s0*va.x + s1*vb.x; o.y = s0*va.y + s1*vb.y;
        o.z = s0*va.z + s1*vb.z; o.w = s0*va.w + s1*vb.w;
        ((float4*)(out + (size_t)t * HD))[h4] = o;
    }
}

// ---------------- host launcher ----------------
extern "C" void kernel_launch(void* const* d_in, const int* in_sizes, int n_in,
                              void* d_out, int out_size) {
    const float* x  = (const float*)d_in[0];
    const float* rw = (const float*)d_in[1];
    const float* w1 = (const float*)d_in[2];
    const float* w3 = (const float*)d_in[3];
    const float* w2 = (const float*)d_in[4];
    float* out = (float*)d_out;

    cudaFuncSetAttribute(moe_persistent, cudaFuncAttributeMaxDynamicSharedMemorySize, RING_SMEM);

    init_small_kernel<<<1, 512>>>();
    moe_persistent<<<NPERS, NTHR, RING_SMEM>>>(out, x, rw, w1, w3, w2);
}

// round 16
// speedup vs baseline: 1.0450x; 1.0450x over previous
#include <cuda_runtime.h>
#include <cuda_fp16.h>
#include <cstdint>
#include <cstddef>

// Problem constants: T=4096, H=I=2048, E=8, top-2
#define TTOK 4096
#define HD   2048
#define NE   8
#define NSLOT (2*TTOK)
#define NSLOTP 9216
#define MTMAX (NSLOTP/128)     // 72

#define BM 128
#define BKC 64
#define NCHUNK (HD/BKC)        // 32
#define NSTG 3
#define NTHR 256

// A block (shared by GU and DN): 128 rows x 144B per 64-k chunk
#define ABLK   18432
// GU B block: 64 k-rows x 144B (64 n + 8 pad halves)  -> per (e, nt64) tile
#define GUB    9216
// DN B block: 64 k-rows x 272B (128 n + 8 pad halves) -> per (e, nt128) tile
#define DNB    17408

#define GU_STG (ABLK + 2*GUB)      // 36864
#define DN_STG (ABLK + DNB)        // 35840
#define RING_STRIDE 36864
#define RING_SMEM (NSTG*RING_STRIDE)   // 110592  (2 CTAs/SM fit: 221184)

#define NPERS 296
#define IT_TOT 4217

// item types
#define TY_XC  0
#define TY_RT  1
#define TY_SC  2
#define TY_W1  3
#define TY_W3  4
#define TY_XG  5
#define TY_GU  6
#define TY_W2  7
#define TY_DN  8

// ---------------- device scratch ----------------
__device__ int   g_counts[NE];
__device__ int   g_offs[NE];
__device__ int   g_ends[NE];
__device__ int   g_cursor[NE];
__device__ int   g_top_idx[NSLOT];
__device__ float g_top_scale[NSLOT];
__device__ int   g_slot_tok[NSLOTP];
__device__ int   g_tok_pos[NSLOT];

// queue + dependency state
__device__ int   g_items[IT_TOT];
__device__ int   g_work;
__device__ int   g_nmt;
__device__ int   g_mt_e[MTMAX];
__device__ int   g_rt_done, g_xc_done, g_scan_done, g_dn_done;
__device__ int   g_xg_done[MTMAX];
__device__ int   g_gu_done[MTMAX];
__device__ int   g_w1c[NE*32];
__device__ int   g_w3c[NE*32];
__device__ int   g_w2c[NE*16];

__device__ __align__(16) __half g_x16[(size_t)TTOK*HD];
__device__ __align__(16) __half g_w1t[(size_t)NE*32*32*(GUB/2)];
__device__ __align__(16) __half g_w3t[(size_t)NE*32*32*(GUB/2)];
__device__ __align__(16) __half g_w2t[(size_t)NE*16*32*(DNB/2)];
__device__ __align__(16) __half g_xg[(size_t)MTMAX*32*(ABLK/2)];
__device__ __align__(16) __half g_actt[(size_t)MTMAX*32*(ABLK/2)];
__device__ __align__(16) float  g_gbuf[(size_t)NSLOTP*HD];

// ---------------- helpers ----------------
__device__ __forceinline__ uint32_t smem_u32(const void* p) {
    return (uint32_t)__cvta_generic_to_shared(p);
}
__device__ __forceinline__ void mbar_init(uint32_t a, uint32_t cnt) {
    asm volatile("mbarrier.init.shared.b64 [%0], %1;" :: "r"(a), "r"(cnt) : "memory");
}
__device__ __forceinline__ void mbar_expect(uint32_t a, uint32_t bytes) {
    asm volatile("mbarrier.arrive.expect_tx.shared.b64 _, [%0], %1;"
                 :: "r"(a), "r"(bytes) : "memory");
}
__device__ __forceinline__ void mbar_wait(uint32_t a, uint32_t parity) {
    asm volatile(
        "{\n\t.reg .pred P;\n\t"
        "WL_%=:\n\t"
        "mbarrier.try_wait.parity.shared::cta.b64 P, [%0], %1;\n\t"
        "@P bra WD_%=;\n\t"
        "bra WL_%=;\n\t"
        "WD_%=:\n\t}"
        :: "r"(a), "r"(parity) : "memory");
}
__device__ __forceinline__ void bulk_g2s(uint32_t dst, const void* src,
                                         uint32_t bytes, uint32_t mbar) {
    asm volatile(
        "cp.async.bulk.shared::cta.global.mbarrier::complete_tx::bytes [%0], [%1], %2, [%3];"
        :: "r"(dst), "l"(src), "r"(bytes), "r"(mbar) : "memory");
}
__device__ __forceinline__ void ldsm_x4(uint32_t (&r)[4], uint32_t addr) {
    asm volatile("ldmatrix.sync.aligned.m8n8.x4.shared.b16 {%0,%1,%2,%3}, [%4];\n"
                 : "=r"(r[0]), "=r"(r[1]), "=r"(r[2]), "=r"(r[3]) : "r"(addr));
}
__device__ __forceinline__ void ldsm_x4_t(uint32_t (&r)[4], uint32_t addr) {
    asm volatile("ldmatrix.sync.aligned.m8n8.x4.trans.shared.b16 {%0,%1,%2,%3}, [%4];\n"
                 : "=r"(r[0]), "=r"(r[1]), "=r"(r[2]), "=r"(r[3]) : "r"(addr));
}
__device__ __forceinline__ void mma16816(float (&c)[4], const uint32_t (&a)[4],
                                         uint32_t b0, uint32_t b1) {
    asm volatile(
        "mma.sync.aligned.m16n8k16.row.col.f32.f16.f16.f32 "
        "{%0,%1,%2,%3}, {%4,%5,%6,%7}, {%8,%9}, {%0,%1,%2,%3};\n"
        : "+f"(c[0]), "+f"(c[1]), "+f"(c[2]), "+f"(c[3])
        : "r"(a[0]), "r"(a[1]), "r"(a[2]), "r"(a[3]), "r"(b0), "r"(b1));
}
__device__ __forceinline__ float silu_mul(float g, float u) {
    return u * (g / (1.f + __expf(-g)));
}
__device__ __forceinline__ uint32_t h2u(__half2 h) { return *(uint32_t*)&h; }
__device__ __forceinline__ int ldvol(const int* p) {
    int v;
    asm volatile("ld.volatile.global.b32 %0, [%1];" : "=r"(v) : "l"(p));
    return v;
}
__device__ __forceinline__ uint4 pack16(float4 v0, float4 v1) {
    uint4 p;
    p.x = h2u(__floats2half2_rn(v0.x, v0.y));
    p.y = h2u(__floats2half2_rn(v0.z, v0.w));
    p.z = h2u(__floats2half2_rn(v1.x, v1.y));
    p.w = h2u(__floats2half2_rn(v1.z, v1.w));
    return p;
}

// ---------------- init: flags + software-pipelined work table ----------------
__global__ void init_small_kernel() {
    int i = threadIdx.x;
    if (i < NE) { g_counts[i] = 0; g_cursor[i] = 0; }
    if (i == 0) { g_work = 0; g_rt_done = 0; g_xc_done = 0; g_scan_done = 0; g_dn_done = 0; }
    if (i < MTMAX) { g_xg_done[i] = 0; g_gu_done[i] = 0; }
    if (i < NE*32) { g_w1c[i] = 0; g_w3c[i] = 0; }
    if (i < NE*16) g_w2c[i] = 0;
    if (i == 0) {
        int n = 0;
#define ADDIT(t, a, b) g_items[n++] = ((t) << 16) | ((a) << 8) | (b)
        for (int j = 0; j < 16; j++) ADDIT(TY_XC, j, 0);
        for (int j = 0; j < 32; j++) ADDIT(TY_RT, j, 0);
        for (int e = 0; e < NE; e++) ADDIT(TY_W1, e, 0);
        for (int e = 0; e < NE; e++) ADDIT(TY_W3, e, 0);
        ADDIT(TY_SC, 0, 0);
        for (int e = 0; e < NE; e++) ADDIT(TY_W1, e, 1);
        for (int e = 0; e < NE; e++) ADDIT(TY_W3, e, 1);
        for (int m = 0; m < MTMAX; m++) ADDIT(TY_XG, m, 0);
        for (int nt = 0; nt < 32; nt++) {
            for (int m = 0; m < MTMAX; m++) ADDIT(TY_GU, m, nt);
            if (nt + 2 < 32) {
                for (int e = 0; e < NE; e++) ADDIT(TY_W1, e, nt + 2);
                for (int e = 0; e < NE; e++) ADDIT(TY_W3, e, nt + 2);
            }
            if (nt >= 16) {
                for (int e = 0; e < NE; e++) ADDIT(TY_W2, e, nt - 16);
            }
        }
        for (int nt2 = 0; nt2 < 16; nt2++)
            for (int m = 0; m < MTMAX; m++) ADDIT(TY_DN, m, nt2);
        // n == 4217 == IT_TOT
    }
}

// ---------------- item bodies (256 threads) ----------------
__device__ void rt_item(const float* __restrict__ x, const float* __restrict__ rw,
                        int it, int tid) {
    const int warp = tid >> 5, lane = tid & 31;
#pragma unroll
    for (int pass = 0; pass < 4; pass++) {
        const int t0 = it * 128 + pass * 32 + warp * 4;
        float acc[4][NE];
#pragma unroll
        for (int j = 0; j < 4; j++)
#pragma unroll
            for (int e = 0; e < NE; e++) acc[j][e] = 0.f;
        const float* xr = x + (size_t)t0 * HD;
        for (int h = lane; h < HD; h += 32) {
            float4 r0 = *(const float4*)(rw + (size_t)h * NE);
            float4 r1 = *(const float4*)(rw + (size_t)h * NE + 4);
            float rv[NE] = {r0.x, r0.y, r0.z, r0.w, r1.x, r1.y, r1.z, r1.w};
#pragma unroll
            for (int j = 0; j < 4; j++) {
                float xv = xr[(size_t)j * HD + h];
#pragma unroll
                for (int e = 0; e < NE; e++) acc[j][e] = fmaf(xv, rv[e], acc[j][e]);
            }
        }
#pragma unroll
        for (int j = 0; j < 4; j++)
#pragma unroll
            for (int e = 0; e < NE; e++) {
#pragma unroll
                for (int o = 16; o; o >>= 1)
                    acc[j][e] += __shfl_xor_sync(0xffffffffu, acc[j][e], o);
            }
        if (lane == 0) {
#pragma unroll
            for (int j = 0; j < 4; j++) {
                int t = t0 + j;
                int i0 = 0; float v0 = acc[j][0];
#pragma unroll
                for (int e = 1; e < NE; e++) if (acc[j][e] > v0) { v0 = acc[j][e]; i0 = e; }
                int i1 = -1; float v1 = -3.4e38f;
#pragma unroll
                for (int e = 0; e < NE; e++)
                    if (e != i0 && acc[j][e] > v1) { v1 = acc[j][e]; i1 = e; }
                float ex = expf(v1 - v0);
                float inv = 1.f / (1.f + ex);
                g_top_idx[2*t]   = i0; g_top_scale[2*t]   = inv;
                g_top_idx[2*t+1] = i1; g_top_scale[2*t+1] = ex * inv;
                atomicAdd(&g_counts[i0], 1);
                atomicAdd(&g_counts[i1], 1);
            }
        }
    }
}

__device__ void xc_item(const float* __restrict__ x, int i, int tid) {
    const float4* s4 = (const float4*)x;
    __half2* d2 = (__half2*)g_x16;
#pragma unroll 4
    for (int j = 0; j < 512; j++) {
        size_t idx = (size_t)i * 131072 + (size_t)j * NTHR + tid;
        float4 v = s4[idx];
        d2[2*idx]   = __floats2half2_rn(v.x, v.y);
        d2[2*idx+1] = __floats2half2_rn(v.z, v.w);
    }
}

__device__ void scan_item(int tid) {
    if (tid == 0) {
        int o = 0;
        for (int e = 0; e < NE; e++) {
            g_offs[e] = o; g_cursor[e] = o; g_ends[e] = o + g_counts[e];
            int padded = (g_counts[e] + 127) & ~127;
            for (int m = o >> 7; m < (o + padded) >> 7; m++) g_mt_e[m] = e;
            o += padded;
        }
        g_nmt = o >> 7;
        for (int m = o >> 7; m < MTMAX; m++) g_mt_e[m] = 0;
    }
    __syncthreads();
    for (int i = tid; i < NSLOTP; i += NTHR) g_slot_tok[i] = -1;
    __syncthreads();
    for (int i = tid; i < NSLOT; i += NTHR) {
        int e = g_top_idx[i];
        int pos = atomicAdd(&g_cursor[e], 1);
        g_slot_tok[pos] = i >> 1;
        g_tok_pos[i] = pos;
    }
}

// w1/w3 convert for (e, nt in 0..31): 2048k x 64n -> blocked (row 144B)
__device__ void wcvt_gu(const float* __restrict__ src, char* base, int e, int nt, int tid) {
    const float4* s4 = (const float4*)(src + (size_t)e * HD * HD);
#pragma unroll 4
    for (int i = 0; i < 64; i++) {
        int u = i * NTHR + tid;           // 0..16383
        int k = u >> 3, nl = u & 7;
        const float4* s = s4 + (size_t)k * 512 + (nt * 8 + nl) * 2;
        uint4 pkt = pack16(s[0], s[1]);
        char* dst = base + ((size_t)((e*32 + nt)*32 + (k >> 6)))*GUB
                  + (size_t)(k & 63)*144 + (size_t)nl*16;
        *(uint4*)dst = pkt;
    }
}

// w2 convert for (e, nt in 0..15): 2048k x 128n -> blocked (row 272B)
__device__ void wcvt_dn(const float* __restrict__ w2, int e, int nt, int tid) {
    const float4* s4 = (const float4*)(w2 + (size_t)e * HD * HD);
#pragma unroll 4
    for (int i = 0; i < 128; i++) {
        int u = i * NTHR + tid;           // 0..32767
        int k = u >> 4, nl = u & 15;
        const float4* s = s4 + (size_t)k * 512 + (nt * 16 + nl) * 2;
        uint4 pkt = pack16(s[0], s[1]);
        char* dst = (char*)g_w2t + ((size_t)((e*16 + nt)*32 + (k >> 6)))*DNB
                  + (size_t)(k & 63)*272 + (size_t)nl*16;
        *(uint4*)dst = pkt;
    }
}

__device__ void xg_tile(int m, int tid) {
#pragma unroll 4
    for (int i = 0; i < 128; i++) {
        int u = i * NTHR + tid;
        int seg = u & 7, c = (u >> 3) & 31, row = u >> 8;
        int tok = g_slot_tok[m * 128 + row];
        uint4 v = make_uint4(0, 0, 0, 0);
        if (tok >= 0) v = *(const uint4*)(g_x16 + (size_t)tok * HD + c * 64 + seg * 8);
        char* dst = (char*)g_xg + ((size_t)m * 32 + c) * ABLK
                  + (size_t)row * 144 + (size_t)seg * 16;
        *(uint4*)dst = v;
    }
}

// ---- GU tile: 128M x 64N dual-mat, 8 warps (2M x 4N), warp 64M x 16N ----
__device__ void gu_tile(char* sm, uint64_t* bars, int m, int nt, int tid) {
    const int e = g_mt_e[m];
    const int row0 = m * 128;
    const int rowEnd = g_ends[e];
    const int n0 = nt * 64;

    const char* aBase  = (const char*)g_xg  + (size_t)m * 32 * ABLK;
    const char* b1Base = (const char*)g_w1t + (size_t)(e*32 + nt) * 32 * GUB;
    const char* b3Base = (const char*)g_w3t + (size_t)(e*32 + nt) * 32 * GUB;

    const uint32_t sb = smem_u32(sm);
    const uint32_t bb = smem_u32(bars);

    if (tid == 0) {
#pragma unroll
        for (int s = 0; s < NSTG; s++) mbar_init(bb + 8*s, 1);
    }
    __syncthreads();
    if (tid == 0) {
#pragma unroll
        for (int p = 0; p < 2; p++) {
            uint32_t st = sb + p * RING_STRIDE, mb = bb + 8*p;
            mbar_expect(mb, GU_STG);
            bulk_g2s(st,              aBase  + (size_t)p * ABLK, ABLK, mb);
            bulk_g2s(st + ABLK,       b1Base + (size_t)p * GUB, GUB, mb);
            bulk_g2s(st + ABLK + GUB, b3Base + (size_t)p * GUB, GUB, mb);
        }
    }

    const int wid = tid >> 5, lane = tid & 31;
    const int wm = wid & 1, wn = wid >> 1;        // 2 M-groups(64) x 4 N-groups(16)
    const int ar = lane & 15, ac = (lane >> 4) * 8;
    const int br = lane & 15, bc = (lane >> 4) * 8;

    float accG[4][2][4], accU[4][2][4];
#pragma unroll
    for (int mt = 0; mt < 4; mt++)
#pragma unroll
        for (int q = 0; q < 2; q++)
#pragma unroll
            for (int r = 0; r < 4; r++) { accG[mt][q][r] = 0.f; accU[mt][q][r] = 0.f; }

    for (int c = 0; c < NCHUNK; c++) {
        int s = c % NSTG;
        mbar_wait(bb + 8*s, (c / NSTG) & 1);
        __syncthreads();
        if (tid == 0 && c + 2 < NCHUNK) {
            int s2 = (c + 2) % NSTG;
            uint32_t st = sb + s2 * RING_STRIDE, mb = bb + 8*s2;
            mbar_expect(mb, GU_STG);
            bulk_g2s(st,              aBase  + (size_t)(c+2) * ABLK, ABLK, mb);
            bulk_g2s(st + ABLK,       b1Base + (size_t)(c+2) * GUB, GUB, mb);
            bulk_g2s(st + ABLK + GUB, b3Base + (size_t)(c+2) * GUB, GUB, mb);
        }
        uint32_t stb = sb + (uint32_t)s * RING_STRIDE;

#pragma unroll
        for (int kk = 0; kk < 4; kk++) {
            uint32_t a[4][4];
#pragma unroll
            for (int mt = 0; mt < 4; mt++) {
                uint32_t aaddr = stb
                    + (uint32_t)((wm * 64 + mt * 16 + ar) * 144 + (kk * 16 + ac) * 2);
                ldsm_x4(a[mt], aaddr);
            }
            uint32_t brow = (uint32_t)((kk * 16 + br) * 144);
            uint32_t coff = (uint32_t)((wn * 16 + bc) * 2);
            uint32_t b1[4], b3[4];
            ldsm_x4_t(b1, stb + ABLK + brow + coff);
            ldsm_x4_t(b3, stb + ABLK + GUB + brow + coff);
#pragma unroll
            for (int mt = 0; mt < 4; mt++) {
                mma16816(accG[mt][0], a[mt], b1[0], b1[1]);
                mma16816(accG[mt][1], a[mt], b1[2], b1[3]);
                mma16816(accU[mt][0], a[mt], b3[0], b3[1]);
                mma16816(accU[mt][1], a[mt], b3[2], b3[3]);
            }
        }
    }

    // epilogue: act = silu(g)*u -> fp16, slot-tiled layout
    const int rIn = lane >> 2, cIn = (lane & 3) * 2;
#pragma unroll
    for (int mt = 0; mt < 4; mt++) {
#pragma unroll
        for (int half = 0; half < 2; half++) {
            int slot = row0 + wm * 64 + mt * 16 + rIn + half * 8;
            if (slot < rowEnd) {
                int srow = slot & 127, smt = slot >> 7;
#pragma unroll
                for (int q = 0; q < 2; q++) {
                    int col = n0 + wn * 16 + q * 8 + cIn;
                    int cch = col >> 6, kl = col & 63;
                    __half* dst = g_actt + ((size_t)smt * 32 + cch) * (ABLK/2)
                                + (size_t)srow * 72 + kl;
                    float a0 = silu_mul(accG[mt][q][half*2],   accU[mt][q][half*2]);
                    float a1 = silu_mul(accG[mt][q][half*2+1], accU[mt][q][half*2+1]);
                    *(__half2*)dst = __floats2half2_rn(a0, a1);
                }
            }
        }
    }
}

// ---- DN tile: 128M x 128N, 8 warps (2M x 4N), warp 64M x 32N ----
__device__ void dn_tile(char* sm, uint64_t* bars, int m, int nt, int tid) {
    const int e = g_mt_e[m];
    const int row0 = m * 128;
    const int rowEnd = g_ends[e];
    const int n0 = nt * 128;

    const char* aBase = (const char*)g_actt + (size_t)m * 32 * ABLK;
    const char* bBase = (const char*)g_w2t + (size_t)(e*16 + nt) * 32 * DNB;

    const uint32_t sb = smem_u32(sm);
    const uint32_t bb = smem_u32(bars);

    if (tid == 0) {
#pragma unroll
        for (int s = 0; s < NSTG; s++) mbar_init(bb + 8*s, 1);
    }
    __syncthreads();
    if (tid == 0) {
#pragma unroll
        for (int p = 0; p < 2; p++) {
            uint32_t st = sb + p * RING_STRIDE, mb = bb + 8*p;
            mbar_expect(mb, DN_STG);
            bulk_g2s(st,        aBase + (size_t)p * ABLK, ABLK, mb);
            bulk_g2s(st + ABLK, bBase + (size_t)p * DNB, DNB, mb);
        }
    }

    const int wid = tid >> 5, lane = tid & 31;
    const int wm = wid & 1, wn = wid >> 1;        // 2 M-groups(64) x 4 N-groups(32)
    const int ar = lane & 15, ac = (lane >> 4) * 8;
    const int br = lane & 15, bc = (lane >> 4) * 8;

    float acc[4][4][4];
#pragma unroll
    for (int mt = 0; mt < 4; mt++)
#pragma unroll
        for (int q = 0; q < 4; q++)
#pragma unroll
            for (int r = 0; r < 4; r++) acc[mt][q][r] = 0.f;

    for (int c = 0; c < NCHUNK; c++) {
        int s = c % NSTG;
        mbar_wait(bb + 8*s, (c / NSTG) & 1);
        __syncthreads();
        if (tid == 0 && c + 2 < NCHUNK) {
            int s2 = (c + 2) % NSTG;
            uint32_t st = sb + s2 * RING_STRIDE, mb = bb + 8*s2;
            mbar_expect(mb, DN_STG);
            bulk_g2s(st,        aBase + (size_t)(c+2) * ABLK, ABLK, mb);
            bulk_g2s(st + ABLK, bBase + (size_t)(c+2) * DNB, DNB, mb);
        }
        uint32_t stb = sb + (uint32_t)s * RING_STRIDE;

#pragma unroll
        for (int kk = 0; kk < 4; kk++) {
            uint32_t a[4][4];
#pragma unroll
            for (int mt = 0; mt < 4; mt++) {
                uint32_t aaddr = stb
                    + (uint32_t)((wm * 64 + mt * 16 + ar) * 144 + (kk * 16 + ac) * 2);
                ldsm_x4(a[mt], aaddr);
            }
            uint32_t brow = (uint32_t)((kk * 16 + br) * 272);
#pragma unroll
            for (int p = 0; p < 2; p++) {
                uint32_t b[4];
                ldsm_x4_t(b, stb + ABLK + brow
                             + (uint32_t)((wn * 32 + p * 16 + bc) * 2));
#pragma unroll
                for (int mt = 0; mt < 4; mt++) {
                    mma16816(acc[mt][2*p],   a[mt], b[0], b[1]);
                    mma16816(acc[mt][2*p+1], a[mt], b[2], b[3]);
                }
            }
        }
    }

    const int rIn = lane >> 2, cIn = (lane & 3) * 2;
#pragma unroll
    for (int mt = 0; mt < 4; mt++) {
#pragma unroll
        for (int half = 0; half < 2; half++) {
            int slot = row0 + wm * 64 + mt * 16 + rIn + half * 8;
            if (slot < rowEnd) {
                float* Cp = g_gbuf + (size_t)slot * HD + n0 + wn * 32 + cIn;
#pragma unroll
                for (int q = 0; q < 4; q++) {
                    float2 v = make_float2(acc[mt][q][half*2], acc[mt][q][half*2+1]);
                    *(float2*)(Cp + q * 8) = v;
                }
            }
        }
    }
}

// ---------------- persistent scheduler: 2 CTAs per SM ----------------
__global__ void __launch_bounds__(NTHR, 2)
moe_persistent(float* __restrict__ out,
               const float* __restrict__ x,  const float* __restrict__ rw,
               const float* __restrict__ w1, const float* __restrict__ w3,
               const float* __restrict__ w2) {
    extern __shared__ __align__(128) char sm[];
    __shared__ __align__(8) uint64_t bars[NSTG];
    __shared__ int sh_w, sh_flag;
    const int tid = threadIdx.x;

    for (;;) {
        if (tid == 0) sh_w = atomicAdd(&g_work, 1);
        __syncthreads();
        int w = sh_w;
        if (w >= IT_TOT) break;
        int item = g_items[w];
        int ty = item >> 16, a = (item >> 8) & 255, b = item & 255;

        switch (ty) {
        case TY_XC:
            xc_item(x, a, tid);
            __threadfence(); __syncthreads();
            if (tid == 0) atomicAdd(&g_xc_done, 1);
            break;
        case TY_RT:
            rt_item(x, rw, a, tid);
            __threadfence(); __syncthreads();
            if (tid == 0) atomicAdd(&g_rt_done, 1);
            break;
        case TY_SC:
            if (tid == 0) { while (ldvol(&g_rt_done) < 32) {} }
            __syncthreads(); __threadfence();
            scan_item(tid);
            __threadfence(); __syncthreads();
            if (tid == 0) atomicExch(&g_scan_done, 1);
            break;
        case TY_W1:
            wcvt_gu(w1, (char*)g_w1t, a, b, tid);
            __threadfence(); __syncthreads();
            if (tid == 0) atomicExch(&g_w1c[a*32 + b], 1);
            break;
        case TY_W3:
            wcvt_gu(w3, (char*)g_w3t, a, b, tid);
            __threadfence(); __syncthreads();
            if (tid == 0) atomicExch(&g_w3c[a*32 + b], 1);
            break;
        case TY_XG:
            if (tid == 0) {
                while (ldvol(&g_scan_done) == 0) {}
                while (ldvol(&g_xc_done) < 16) {}
                sh_flag = (a < g_nmt);
            }
            __syncthreads(); __threadfence();
            if (sh_flag) xg_tile(a, tid);
            __threadfence(); __syncthreads();
            if (tid == 0) atomicExch(&g_xg_done[a], 1);
            break;
        case TY_GU:
            if (tid == 0) {
                while (ldvol(&g_xg_done[a]) == 0) {}
                int e = g_mt_e[a];
                while (ldvol(&g_w1c[e*32 + b]) == 0) {}
                while (ldvol(&g_w3c[e*32 + b]) == 0) {}
                sh_flag = (a < g_nmt);
            }
            __syncthreads(); __threadfence();
            if (sh_flag) gu_tile(sm, bars, a, b, tid);
            __threadfence(); __syncthreads();
            if (tid == 0) atomicAdd(&g_gu_done[a], 1);
            break;
        case TY_W2:
            wcvt_dn(w2, a, b, tid);
            __threadfence(); __syncthreads();
            if (tid == 0) atomicExch(&g_w2c[a*16 + b], 1);
            break;
        default: // TY_DN
            if (tid == 0) {
                while (ldvol(&g_gu_done[a]) < 32) {}
                int e = g_mt_e[a];
                while (ldvol(&g_w2c[e*16 + b]) == 0) {}
                sh_flag = (a < g_nmt);
            }
            __syncthreads(); __threadfence();
            if (sh_flag) dn_tile(sm, bars, a, b, tid);
            __threadfence(); __syncthreads();
            if (tid == 0) atomicAdd(&g_dn_done, 1);
            break;
        }
        __syncthreads();
    }

    // combine: out[t] = s0*y[p0] + s1*y[p1]
    if (tid == 0) { while (ldvol(&g_dn_done) < MTMAX * 16) {} }
    __syncthreads(); __threadfence();
    const int N4 = TTOK * HD / 4;
    for (int i = blockIdx.x * NTHR + tid; i < N4; i += NPERS * NTHR) {
        int t  = i >> 9;
        int h4 = i & 511;
        float s0 = g_top_scale[2*t], s1 = g_top_scale[2*t+1];
        int p0 = g_tok_pos[2*t], p1 = g_tok_pos[2*t+1];
        float4 va = __ldcg((const float4*)(g_gbuf + (size_t)p0 * HD) + h4);
        float4 vb = __ldcg((const float4*)(g_gbuf + (size_t)p1 * HD) + h4);
        float4 o;
        o.x = s0*va.x + s1*vb.x; o.y = s0*va.y + s1*vb.y;
        o.z = s0*va.z + s1*vb.z; o.w = s0*va.w + s1*vb.w;
        ((float4*)(out + (size_t)t * HD))[h4] = o;
    }
}

// ---------------- host launcher ----------------
extern "C" void kernel_launch(void* const* d_in, const int* in_sizes, int n_in,
                              void* d_out, int out_size) {
    const float* x  = (const float*)d_in[0];
    const float* rw = (const float*)d_in[1];
    const float* w1 = (const float*)d_in[2];
    const float* w3 = (const float*)d_in[3];
    const float* w2 = (const float*)d_in[4];
    float* out = (float*)d_out;

    cudaFuncSetAttribute(moe_persistent, cudaFuncAttributeMaxDynamicSharedMemorySize, RING_SMEM);

    init_small_kernel<<<1, 512>>>();
    moe_persistent<<<NPERS, NTHR, RING_SMEM>>>(out, x, rw, w1, w3, w2);
}

// round 17
// speedup vs baseline: 1.1568x; 1.1070x over previous
#include <cuda_runtime.h>
#include <cuda_fp16.h>
#include <cstdint>
#include <cstddef>

// Problem constants: T=4096, H=I=2048, E=8, top-2
#define TTOK 4096
#define HD   2048
#define NE   8
#define NSLOT (2*TTOK)
#define NSLOTP 9216
#define MTMAX (NSLOTP/128)     // 72

#define BM 128
#define BKC 64
#define NCHUNK (HD/BKC)        // 32
#define NSTG 3

// gate+up: 128M x 128N dual-B
#define GU_ABLK 18432          // 128 rows x 144B
#define GU_BBLK 17408          // 64 rows x 272B
#define GU_STG  (GU_ABLK + 2*GU_BBLK)   // 53248
// down: 128M x 256N
#define DN_ABLK 18432
#define DN_BBLK 33792          // 64 rows x 528B
#define DN_STG  (DN_ABLK + DN_BBLK)     // 52224
#define RING_SMEM (NSTG*GU_STG)         // 159744

#define NPERS 148
#define IT_TOT 2169

// item types
#define TY_XC  0
#define TY_RT  1
#define TY_SC  2
#define TY_W1  3
#define TY_W3  4
#define TY_XG  5
#define TY_GU  6
#define TY_W2  7
#define TY_DN  8

// ---------------- device scratch ----------------
__device__ int   g_counts[NE];
__device__ int   g_offs[NE];
__device__ int   g_ends[NE];
__device__ int   g_cursor[NE];
__device__ int   g_top_idx[NSLOT];
__device__ float g_top_scale[NSLOT];
__device__ int   g_slot_tok[NSLOTP];
__device__ float g_slot_scale[NSLOTP];
__device__ int   g_tok_pos[NSLOT];

// queue + dependency state
__device__ int   g_items[IT_TOT];
__device__ int   g_work;
__device__ int   g_nmt;
__device__ int   g_mt_e[MTMAX];
__device__ int   g_rt_done, g_xc_done, g_scan_done, g_dn_done;
__device__ int   g_xg_done[MTMAX];
__device__ int   g_gu_done[MTMAX];
__device__ int   g_w1c[NE*16];
__device__ int   g_w3c[NE*16];
__device__ int   g_w2c[NE*8];

__device__ __align__(16) __half g_x16[(size_t)TTOK*HD];
__device__ __align__(16) __half g_w1t[(size_t)NE*16*32*(GU_BBLK/2)];
__device__ __align__(16) __half g_w3t[(size_t)NE*16*32*(GU_BBLK/2)];
__device__ __align__(16) __half g_w2t[(size_t)NE*8*32*(DN_BBLK/2)];
__device__ __align__(16) __half g_xg[(size_t)MTMAX*32*(GU_ABLK/2)];
__device__ __align__(16) __half g_actt[(size_t)MTMAX*32*(DN_ABLK/2)];

// ---------------- helpers ----------------
__device__ __forceinline__ uint32_t smem_u32(const void* p) {
    return (uint32_t)__cvta_generic_to_shared(p);
}
__device__ __forceinline__ void mbar_init(uint32_t a, uint32_t cnt) {
    asm volatile("mbarrier.init.shared.b64 [%0], %1;" :: "r"(a), "r"(cnt) : "memory");
}
__device__ __forceinline__ void mbar_expect(uint32_t a, uint32_t bytes) {
    asm volatile("mbarrier.arrive.expect_tx.shared.b64 _, [%0], %1;"
                 :: "r"(a), "r"(bytes) : "memory");
}
__device__ __forceinline__ void mbar_wait(uint32_t a, uint32_t parity) {
    asm volatile(
        "{\n\t.reg .pred P;\n\t"
        "WL_%=:\n\t"
        "mbarrier.try_wait.parity.shared::cta.b64 P, [%0], %1;\n\t"
        "@P bra WD_%=;\n\t"
        "bra WL_%=;\n\t"
        "WD_%=:\n\t}"
        :: "r"(a), "r"(parity) : "memory");
}
__device__ __forceinline__ void bulk_g2s(uint32_t dst, const void* src,
                                         uint32_t bytes, uint32_t mbar) {
    asm volatile(
        "cp.async.bulk.shared::cta.global.mbarrier::complete_tx::bytes [%0], [%1], %2, [%3];"
        :: "r"(dst), "l"(src), "r"(bytes), "r"(mbar) : "memory");
}
__device__ __forceinline__ void ldsm_x4(uint32_t (&r)[4], uint32_t addr) {
    asm volatile("ldmatrix.sync.aligned.m8n8.x4.shared.b16 {%0,%1,%2,%3}, [%4];\n"
                 : "=r"(r[0]), "=r"(r[1]), "=r"(r[2]), "=r"(r[3]) : "r"(addr));
}
__device__ __forceinline__ void ldsm_x4_t(uint32_t (&r)[4], uint32_t addr) {
    asm volatile("ldmatrix.sync.aligned.m8n8.x4.trans.shared.b16 {%0,%1,%2,%3}, [%4];\n"
                 : "=r"(r[0]), "=r"(r[1]), "=r"(r[2]), "=r"(r[3]) : "r"(addr));
}
__device__ __forceinline__ void mma16816(float (&c)[4], const uint32_t (&a)[4],
                                         uint32_t b0, uint32_t b1) {
    asm volatile(
        "mma.sync.aligned.m16n8k16.row.col.f32.f16.f16.f32 "
        "{%0,%1,%2,%3}, {%4,%5,%6,%7}, {%8,%9}, {%0,%1,%2,%3};\n"
        : "+f"(c[0]), "+f"(c[1]), "+f"(c[2]), "+f"(c[3])
        : "r"(a[0]), "r"(a[1]), "r"(a[2]), "r"(a[3]), "r"(b0), "r"(b1));
}
__device__ __forceinline__ void red_add(float* p, float v) {
    asm volatile("red.global.add.f32 [%0], %1;" :: "l"(p), "f"(v) : "memory");
}
__device__ __forceinline__ float silu_mul(float g, float u) {
    return u * (g / (1.f + __expf(-g)));
}
__device__ __forceinline__ uint32_t h2u(__half2 h) { return *(uint32_t*)&h; }
__device__ __forceinline__ int ldvol(const int* p) {
    int v;
    asm volatile("ld.volatile.global.b32 %0, [%1];" : "=r"(v) : "l"(p));
    return v;
}
__device__ __forceinline__ uint4 pack16(float4 v0, float4 v1) {
    uint4 p;
    p.x = h2u(__floats2half2_rn(v0.x, v0.y));
    p.y = h2u(__floats2half2_rn(v0.z, v0.w));
    p.z = h2u(__floats2half2_rn(v1.x, v1.y));
    p.w = h2u(__floats2half2_rn(v1.z, v1.w));
    return p;
}

// ---------------- init: flags + software-pipelined work table ----------------
__global__ void init_small_kernel() {
    int i = threadIdx.x;
    if (i < NE) { g_counts[i] = 0; g_cursor[i] = 0; }
    if (i == 0) { g_work = 0; g_rt_done = 0; g_xc_done = 0; g_scan_done = 0; g_dn_done = 0; }
    if (i < MTMAX) { g_xg_done[i] = 0; g_gu_done[i] = 0; }
    if (i < NE*16) { g_w1c[i] = 0; g_w3c[i] = 0; }
    if (i < NE*8) g_w2c[i] = 0;
    if (i == 0) {
        int n = 0;
#define ADDIT(t, a, b) g_items[n++] = ((t) << 16) | ((a) << 8) | (b)
        for (int j = 0; j < 16; j++) ADDIT(TY_XC, j, 0);
        for (int j = 0; j < 32; j++) ADDIT(TY_RT, j, 0);
        for (int e = 0; e < NE; e++) ADDIT(TY_W1, e, 0);
        for (int e = 0; e < NE; e++) ADDIT(TY_W3, e, 0);
        ADDIT(TY_SC, 0, 0);
        for (int e = 0; e < NE; e++) ADDIT(TY_W1, e, 1);
        for (int e = 0; e < NE; e++) ADDIT(TY_W3, e, 1);
        for (int m = 0; m < MTMAX; m++) ADDIT(TY_XG, m, 0);
        for (int nt = 0; nt < 16; nt++) {
            for (int m = 0; m < MTMAX; m++) ADDIT(TY_GU, m, nt);
            if (nt + 2 < 16) {
                for (int e = 0; e < NE; e++) ADDIT(TY_W1, e, nt + 2);
                for (int e = 0; e < NE; e++) ADDIT(TY_W3, e, nt + 2);
            }
            if (nt >= 8) {
                for (int e = 0; e < NE; e++) ADDIT(TY_W2, e, nt - 8);
            }
        }
        for (int nt2 = 0; nt2 < 8; nt2++)
            for (int m = 0; m < MTMAX; m++) ADDIT(TY_DN, m, nt2);
    }
}

// ---------------- item bodies ----------------
__device__ void rt_item(const float* __restrict__ x, const float* __restrict__ rw,
                        int it, int tid) {
    const int warp = tid >> 5, lane = tid & 31;
#pragma unroll
    for (int pass = 0; pass < 2; pass++) {
        const int t0 = it * 128 + pass * 64 + warp * 4;
        float acc[4][NE];
#pragma unroll
        for (int j = 0; j < 4; j++)
#pragma unroll
            for (int e = 0; e < NE; e++) acc[j][e] = 0.f;
        const float* xr = x + (size_t)t0 * HD;
        for (int h = lane; h < HD; h += 32) {
            float4 r0 = *(const float4*)(rw + (size_t)h * NE);
            float4 r1 = *(const float4*)(rw + (size_t)h * NE + 4);
            float rv[NE] = {r0.x, r0.y, r0.z, r0.w, r1.x, r1.y, r1.z, r1.w};
#pragma unroll
            for (int j = 0; j < 4; j++) {
                float xv = xr[(size_t)j * HD + h];
#pragma unroll
                for (int e = 0; e < NE; e++) acc[j][e] = fmaf(xv, rv[e], acc[j][e]);
            }
        }
#pragma unroll
        for (int j = 0; j < 4; j++)
#pragma unroll
            for (int e = 0; e < NE; e++) {
#pragma unroll
                for (int o = 16; o; o >>= 1)
                    acc[j][e] += __shfl_xor_sync(0xffffffffu, acc[j][e], o);
            }
        if (lane == 0) {
#pragma unroll
            for (int j = 0; j < 4; j++) {
                int t = t0 + j;
                int i0 = 0; float v0 = acc[j][0];
#pragma unroll
                for (int e = 1; e < NE; e++) if (acc[j][e] > v0) { v0 = acc[j][e]; i0 = e; }
                int i1 = -1; float v1 = -3.4e38f;
#pragma unroll
                for (int e = 0; e < NE; e++)
                    if (e != i0 && acc[j][e] > v1) { v1 = acc[j][e]; i1 = e; }
                float ex = expf(v1 - v0);
                float inv = 1.f / (1.f + ex);
                g_top_idx[2*t]   = i0; g_top_scale[2*t]   = inv;
                g_top_idx[2*t+1] = i1; g_top_scale[2*t+1] = ex * inv;
                atomicAdd(&g_counts[i0], 1);
                atomicAdd(&g_counts[i1], 1);
            }
        }
    }
}

__device__ void xc_item(const float* __restrict__ x, int i, int tid) {
    const float4* s4 = (const float4*)x;
    __half2* d2 = (__half2*)g_x16;
#pragma unroll 4
    for (int j = 0; j < 256; j++) {
        size_t idx = (size_t)i * 131072 + (size_t)j * 512 + tid;
        float4 v = s4[idx];
        d2[2*idx]   = __floats2half2_rn(v.x, v.y);
        d2[2*idx+1] = __floats2half2_rn(v.z, v.w);
    }
}

__device__ void scan_item(int tid) {
    if (tid == 0) {
        int o = 0;
        for (int e = 0; e < NE; e++) {
            g_offs[e] = o; g_cursor[e] = o; g_ends[e] = o + g_counts[e];
            int padded = (g_counts[e] + 127) & ~127;
            for (int m = o >> 7; m < (o + padded) >> 7; m++) g_mt_e[m] = e;
            o += padded;
        }
        g_nmt = o >> 7;
        for (int m = o >> 7; m < MTMAX; m++) g_mt_e[m] = 0;
    }
    __syncthreads();
    for (int i = tid; i < NSLOTP; i += 512) g_slot_tok[i] = -1;
    __syncthreads();
    for (int i = tid; i < NSLOT; i += 512) {
        int e = g_top_idx[i];
        int pos = atomicAdd(&g_cursor[e], 1);
        g_slot_tok[pos] = i >> 1;
        g_slot_scale[pos] = g_top_scale[i];
        g_tok_pos[i] = pos;
    }
}

__device__ void wcvt_gu(const float* __restrict__ src, char* base, int e, int nt, int tid) {
    const float4* s4 = (const float4*)(src + (size_t)e * HD * HD);
#pragma unroll 4
    for (int i = 0; i < 64; i++) {
        int u = i * 512 + tid;
        int k = u >> 4, nl = u & 15;
        const float4* s = s4 + (size_t)k * 512 + (nt * 16 + nl) * 2;
        uint4 pkt = pack16(s[0], s[1]);
        char* dst = base + ((size_t)((e*16 + nt)*32 + (k >> 6)))*GU_BBLK
                  + (size_t)(k & 63)*272 + (size_t)nl*16;
        *(uint4*)dst = pkt;
    }
}

__device__ void wcvt_dn(const float* __restrict__ w2, int e, int nt2, int tid) {
    const float4* s4 = (const float4*)(w2 + (size_t)e * HD * HD);
#pragma unroll 4
    for (int i = 0; i < 128; i++) {
        int u = i * 512 + tid;
        int k = u >> 5, nl = u & 31;
        const float4* s = s4 + (size_t)k * 512 + (nt2 * 32 + nl) * 2;
        uint4 pkt = pack16(s[0], s[1]);
        char* dst = (char*)g_w2t + ((size_t)((e*8 + nt2)*32 + (k >> 6)))*DN_BBLK
                  + (size_t)(k & 63)*528 + (size_t)nl*16;
        *(uint4*)dst = pkt;
    }
}

__device__ void xg_tile(int m, int tid) {
#pragma unroll 4
    for (int i = 0; i < 64; i++) {
        int u = i * 512 + tid;
        int seg = u & 7, c = (u >> 3) & 31, row = u >> 8;
        int tok = g_slot_tok[m * 128 + row];
        uint4 v = make_uint4(0, 0, 0, 0);
        if (tok >= 0) v = *(const uint4*)(g_x16 + (size_t)tok * HD + c * 64 + seg * 8);
        char* dst = (char*)g_xg + ((size_t)m * 32 + c) * GU_ABLK
                  + (size_t)row * 144 + (size_t)seg * 16;
        *(uint4*)dst = v;
    }
}

__device__ void gu_tile(char* sm, uint64_t* bars, int m, int nt, int tid) {
    const int e = g_mt_e[m];
    const int row0 = m * 128;
    const int rowEnd = g_ends[e];
    const int n0 = nt * 128;

    const char* aBase  = (const char*)g_xg  + (size_t)m * 32 * GU_ABLK;
    const char* b1Base = (const char*)g_w1t + (size_t)(e*16 + nt) * 32 * GU_BBLK;
    const char* b3Base = (const char*)g_w3t + (size_t)(e*16 + nt) * 32 * GU_BBLK;

    const uint32_t sb = smem_u32(sm);
    const uint32_t bb = smem_u32(bars);

    if (tid == 0) {
#pragma unroll
        for (int s = 0; s < NSTG; s++) mbar_init(bb + 8*s, 1);
    }
    __syncthreads();
    if (tid == 0) {
#pragma unroll
        for (int p = 0; p < 2; p++) {
            uint32_t st = sb + p * GU_STG, mb = bb + 8*p;
            mbar_expect(mb, GU_STG);
            bulk_g2s(st,                     aBase  + (size_t)p * GU_ABLK, GU_ABLK, mb);
            bulk_g2s(st + GU_ABLK,           b1Base + (size_t)p * GU_BBLK, GU_BBLK, mb);
            bulk_g2s(st + GU_ABLK + GU_BBLK, b3Base + (size_t)p * GU_BBLK, GU_BBLK, mb);
        }
    }

    const int wid = tid >> 5, lane = tid & 31;
    const int wm = wid & 3, wn = wid >> 2;
    const int ar = lane & 15, ac = (lane >> 4) * 8;
    const int br = lane & 15, bc = (lane >> 4) * 8;

    float accG[2][4][4], accU[2][4][4];
#pragma unroll
    for (int mt = 0; mt < 2; mt++)
#pragma unroll
        for (int q4 = 0; q4 < 4; q4++)
#pragma unroll
            for (int q = 0; q < 4; q++) { accG[mt][q4][q] = 0.f; accU[mt][q4][q] = 0.f; }

    for (int c = 0; c < NCHUNK; c++) {
        int s = c % NSTG;
        mbar_wait(bb + 8*s, (c / NSTG) & 1);
        __syncthreads();
        if (tid == 0 && c + 2 < NCHUNK) {
            int s2 = (c + 2) % NSTG;
            uint32_t st = sb + s2 * GU_STG, mb = bb + 8*s2;
            mbar_expect(mb, GU_STG);
            bulk_g2s(st,                     aBase  + (size_t)(c+2) * GU_ABLK, GU_ABLK, mb);
            bulk_g2s(st + GU_ABLK,           b1Base + (size_t)(c+2) * GU_BBLK, GU_BBLK, mb);
            bulk_g2s(st + GU_ABLK + GU_BBLK, b3Base + (size_t)(c+2) * GU_BBLK, GU_BBLK, mb);
        }
        uint32_t stb = sb + (uint32_t)s * GU_STG;

#pragma unroll
        for (int kk = 0; kk < 4; kk++) {
            uint32_t a[2][4];
#pragma unroll
            for (int mt = 0; mt < 2; mt++) {
                uint32_t aaddr = stb
                    + (uint32_t)((wm * 32 + mt * 16 + ar) * 144 + (kk * 16 + ac) * 2);
                ldsm_x4(a[mt], aaddr);
            }
            uint32_t brow = (uint32_t)((kk * 16 + br) * 272);
#pragma unroll
            for (int p = 0; p < 2; p++) {
                uint32_t coff = (uint32_t)((wn * 32 + p * 16 + bc) * 2);
                uint32_t b1[4], b3[4];
                ldsm_x4_t(b1, stb + GU_ABLK + brow + coff);
                ldsm_x4_t(b3, stb + GU_ABLK + GU_BBLK + brow + coff);
                mma16816(accG[0][2*p],   a[0], b1[0], b1[1]);
                mma16816(accG[0][2*p+1], a[0], b1[2], b1[3]);
                mma16816(accG[1][2*p],   a[1], b1[0], b1[1]);
                mma16816(accG[1][2*p+1], a[1], b1[2], b1[3]);
                mma16816(accU[0][2*p],   a[0], b3[0], b3[1]);
                mma16816(accU[0][2*p+1], a[0], b3[2], b3[3]);
                mma16816(accU[1][2*p],   a[1], b3[0], b3[1]);
                mma16816(accU[1][2*p+1], a[1], b3[2], b3[3]);
            }
        }
    }

    const int rIn = lane >> 2, cIn = (lane & 3) * 2;
#pragma unroll
    for (int mt = 0; mt < 2; mt++) {
#pragma unroll
        for (int half = 0; half < 2; half++) {
            int slot = row0 + wm * 32 + mt * 16 + rIn + half * 8;
            if (slot < rowEnd) {
                int srow = slot & 127, smt = slot >> 7;
#pragma unroll
                for (int q4 = 0; q4 < 4; q4++) {
                    int col = n0 + wn * 32 + q4 * 8 + cIn;
                    int cch = col >> 6, kl = col & 63;
                    __half* dst = g_actt + ((size_t)smt * 32 + cch) * (DN_ABLK/2)
                                + (size_t)srow * 72 + kl;
                    float a0 = silu_mul(accG[mt][q4][half*2],   accU[mt][q4][half*2]);
                    float a1 = silu_mul(accG[mt][q4][half*2+1], accU[mt][q4][half*2+1]);
                    *(__half2*)dst = __floats2half2_rn(a0, a1);
                }
            }
        }
    }
}

// DN tile: epilogue fuses scale + combine via red.global.add (exactly 2 adds per out elem)
__device__ void dn_tile(char* sm, uint64_t* bars, int m, int nt, int tid,
                        float* __restrict__ out) {
    const int e = g_mt_e[m];
    const int row0 = m * 128;
    const int rowEnd = g_ends[e];
    const int n0 = nt * 256;

    const char* aBase = (const char*)g_actt + (size_t)m * 32 * DN_ABLK;
    const char* bBase = (const char*)g_w2t + (size_t)(e*8 + nt) * 32 * DN_BBLK;

    const uint32_t sb = smem_u32(sm);
    const uint32_t bb = smem_u32(bars);

    if (tid == 0) {
#pragma unroll
        for (int s = 0; s < NSTG; s++) mbar_init(bb + 8*s, 1);
    }
    __syncthreads();
    if (tid == 0) {
#pragma unroll
        for (int p = 0; p < 2; p++) {
            uint32_t st = sb + p * DN_STG, mb = bb + 8*p;
            mbar_expect(mb, DN_STG);
            bulk_g2s(st,           aBase + (size_t)p * DN_ABLK, DN_ABLK, mb);
            bulk_g2s(st + DN_ABLK, bBase + (size_t)p * DN_BBLK, DN_BBLK, mb);
        }
    }

    const int wid = tid >> 5, lane = tid & 31;
    const int wm = wid & 3, wn = wid >> 2;
    const int ar = lane & 15, ac = (lane >> 4) * 8;
    const int br = lane & 15, bc = (lane >> 4) * 8;

    float acc[2][8][4];
#pragma unroll
    for (int mt = 0; mt < 2; mt++)
#pragma unroll
        for (int q8 = 0; q8 < 8; q8++)
#pragma unroll
            for (int q = 0; q < 4; q++) acc[mt][q8][q] = 0.f;

    for (int c = 0; c < NCHUNK; c++) {
        int s = c % NSTG;
        mbar_wait(bb + 8*s, (c / NSTG) & 1);
        __syncthreads();
        if (tid == 0 && c + 2 < NCHUNK) {
            int s2 = (c + 2) % NSTG;
            uint32_t st = sb + s2 * DN_STG, mb = bb + 8*s2;
            mbar_expect(mb, DN_STG);
            bulk_g2s(st,           aBase + (size_t)(c+2) * DN_ABLK, DN_ABLK, mb);
            bulk_g2s(st + DN_ABLK, bBase + (size_t)(c+2) * DN_BBLK, DN_BBLK, mb);
        }
        uint32_t stb = sb + (uint32_t)s * DN_STG;

#pragma unroll
        for (int kk = 0; kk < 4; kk++) {
            uint32_t a[2][4];
#pragma unroll
            for (int mt = 0; mt < 2; mt++) {
                uint32_t aaddr = stb
                    + (uint32_t)((wm * 32 + mt * 16 + ar) * 144 + (kk * 16 + ac) * 2);
                ldsm_x4(a[mt], aaddr);
            }
#pragma unroll
            for (int p = 0; p < 4; p++) {
                uint32_t b[4];
                uint32_t baddr = stb + DN_ABLK
                    + (uint32_t)((kk * 16 + br) * 528 + (wn * 64 + p * 16 + bc) * 2);
                ldsm_x4_t(b, baddr);
                mma16816(acc[0][2*p],   a[0], b[0], b[1]);
                mma16816(acc[0][2*p+1], a[0], b[2], b[3]);
                mma16816(acc[1][2*p],   a[1], b[0], b[1]);
                mma16816(acc[1][2*p+1], a[1], b[2], b[3]);
            }
        }
    }

    const int rIn = lane >> 2, cIn = (lane & 3) * 2;
#pragma unroll
    for (int mt = 0; mt < 2; mt++) {
#pragma unroll
        for (int half = 0; half < 2; half++) {
            int slot = row0 + wm * 32 + mt * 16 + rIn + half * 8;
            if (slot < rowEnd) {
                int tok = g_slot_tok[slot];
                float sc = g_slot_scale[slot];
                float* Cp = out + (size_t)tok * HD + n0 + wn * 64 + cIn;
#pragma unroll
                for (int q8 = 0; q8 < 8; q8++) {
                    red_add(Cp + q8 * 8,     sc * acc[mt][q8][half*2]);
                    red_add(Cp + q8 * 8 + 1, sc * acc[mt][q8][half*2+1]);
                }
            }
        }
    }
}

// ---------------- persistent table-driven scheduler ----------------
__global__ void __launch_bounds__(512, 1)
moe_persistent(float* __restrict__ out,
               const float* __restrict__ x,  const float* __restrict__ rw,
               const float* __restrict__ w1, const float* __restrict__ w3,
               const float* __restrict__ w2) {
    extern __shared__ __align__(128) char sm[];
    __shared__ __align__(8) uint64_t bars[NSTG];
    __shared__ int sh_w, sh_flag;
    const int tid = threadIdx.x;

    for (;;) {
        if (tid == 0) sh_w = atomicAdd(&g_work, 1);
        __syncthreads();
        int w = sh_w;
        if (w >= IT_TOT) break;
        int item = g_items[w];
        int ty = item >> 16, a = (item >> 8) & 255, b = item & 255;

        switch (ty) {
        case TY_XC:
            xc_item(x, a, tid);
            __threadfence(); __syncthreads();
            if (tid == 0) atomicAdd(&g_xc_done, 1);
            break;
        case TY_RT:
            rt_item(x, rw, a, tid);
            __threadfence(); __syncthreads();
            if (tid == 0) atomicAdd(&g_rt_done, 1);
            break;
        case TY_SC:
            if (tid == 0) { while (ldvol(&g_rt_done) < 32) {} }
            __syncthreads(); __threadfence();
            scan_item(tid);
            __threadfence(); __syncthreads();
            if (tid == 0) atomicExch(&g_scan_done, 1);
            break;
        case TY_W1:
            wcvt_gu(w1, (char*)g_w1t, a, b, tid);
            __threadfence(); __syncthreads();
            if (tid == 0) atomicExch(&g_w1c[a*16 + b], 1);
            break;
        case TY_W3:
            wcvt_gu(w3, (char*)g_w3t, a, b, tid);
            __threadfence(); __syncthreads();
            if (tid == 0) atomicExch(&g_w3c[a*16 + b], 1);
            break;
        case TY_XG:
            if (tid == 0) {
                while (ldvol(&g_scan_done) == 0) {}
                while (ldvol(&g_xc_done) < 16) {}
                sh_flag = (a < g_nmt);
            }
            __syncthreads(); __threadfence();
            if (sh_flag) xg_tile(a, tid);
            __threadfence(); __syncthreads();
            if (tid == 0) atomicExch(&g_xg_done[a], 1);
            break;
        case TY_GU:
            if (tid == 0) {
                while (ldvol(&g_xg_done[a]) == 0) {}
                int e = g_mt_e[a];
                while (ldvol(&g_w1c[e*16 + b]) == 0) {}
                while (ldvol(&g_w3c[e*16 + b]) == 0) {}
                sh_flag = (a < g_nmt);
            }
            __syncthreads(); __threadfence();
            if (sh_flag) gu_tile(sm, bars, a, b, tid);
            __threadfence(); __syncthreads();
            if (tid == 0) atomicAdd(&g_gu_done[a], 1);
            break;
        case TY_W2:
            wcvt_dn(w2, a, b, tid);
            __threadfence(); __syncthreads();
            if (tid == 0) atomicExch(&g_w2c[a*8 + b], 1);
            break;
        default: // TY_DN
            if (tid == 0) {
                while (ldvol(&g_gu_done[a]) < 16) {}
                int e = g_mt_e[a];
                while (ldvol(&g_w2c[e*8 + b]) == 0) {}
                sh_flag = (a < g_nmt);
            }
            __syncthreads(); __threadfence();
            if (sh_flag) dn_tile(sm, bars, a, b, tid, out);
            __threadfence(); __syncthreads();
            if (tid == 0) atomicAdd(&g_dn_done, 1);
            break;
        }
        __syncthreads();
    }
}

// ---------------- host launcher ----------------
extern "C" void kernel_launch(void* const* d_in, const int* in_sizes, int n_in,
                              void* d_out, int out_size) {
    const float* x  = (const float*)d_in[0];
    const float* rw = (const float*)d_in[1];
    const float* w1 = (const float*)d_in[2];
    const float* w3 = (const float*)d_in[3];
    const float* w2 = (const float*)d_in[4];
    float* out = (float*)d_out;

    cudaFuncSetAttribute(moe_persistent, cudaFuncAttributeMaxDynamicSharedMemorySize, RING_SMEM);

    cudaMemsetAsync(out, 0, (size_t)out_size * sizeof(float), 0);
    init_small_kernel<<<1, 512>>>();
    moe_persistent<<<NPERS, 512, RING_SMEM>>>(out, x, rw, w1, w3, w2);
}